// round 9
// baseline (speedup 1.0000x reference)
#include <cuda_runtime.h>
#include <cstdint>

#define CC   4
#define HH   4096
#define WW   4096
#define NPIX (HH*WW)          // per-channel pixels: 16777216
#define TT   8
#define THW  512
#define BINS 256
#define AREA (THW*THW)        // 262144
#define CLV  40960            // int(40.0 * AREA / BINS)
#define MMB  1024             // fallback minmax blocks per channel
#define SROWS 8               // rows per apply strip
#define QH   16               // 256-px halves per dim
#define NBLK 512              // persistent grid size (<= 148*4 co-resident)

// ---------------- scratch (static device globals; no allocation) ------------
__device__ unsigned char      g_q[(size_t)CC * NPIX];        // fallback path only
__device__ unsigned char      g_m[(size_t)CC * NPIX / 4];    // fallback path only
__device__ int                g_qh[CC][QH][QH][BINS];        // quadrant histograms
__device__ unsigned char      g_lut[CC][TT*TT][BINS];
__device__ float2             g_part[CC * MMB];              // per-block (min,max) partials
__device__ int                g_vmin2[CC], g_vmax2[CC];      // float bits (y>=0 -> int trick)
__device__ unsigned int       g_nm[CC];                      // masked-pixel count
__device__ unsigned int       g_barcnt = 0;                  // barrier arrival counter
__device__ unsigned int       g_barsense = 0;                // barrier sense (monotone)

#define F_INF  __int_as_float(0x7F800000)
#define F_NINF __int_as_float((int)0xFF800000)

__device__ __forceinline__ unsigned int packbf(float lo, float hi) {
    return (__float_as_uint(lo) >> 16) | (__float_as_uint(hi) & 0xFFFF0000u);
}

// sense-reversing grid barrier; counter self-resets via atomicInc wrap,
// sense compared by equality -> safe across graph replays.
__device__ __forceinline__ void gbar() {
    __syncthreads();
    if (threadIdx.x == 0) {
        __threadfence();
        unsigned int s = *(volatile unsigned int*)&g_barsense;
        if (atomicInc(&g_barcnt, NBLK - 1) == NBLK - 1) {
            __threadfence();
            *(volatile unsigned int*)&g_barsense = s + 1u;
        } else {
            while (*(volatile unsigned int*)&g_barsense == s) __nanosleep(64);
        }
        __threadfence();
    }
    __syncthreads();
}

// ============================ FUSED PERSISTENT KERNEL ========================
__global__ void __launch_bounds__(256, 4) k_fused(const float* __restrict__ X,
                                                  float* __restrict__ out) {
    __shared__ int           sh[QH * BINS];      // 16 KB quant hist
    __shared__ uint2         lutP[9 * BINS];     // 18 KB apply LUT
    __shared__ unsigned int  sa[BINS], sb[BINS]; // stats scans
    __shared__ int           ssc[BINS];          // clip/CDF scan
    __shared__ float         smn[8], smx[8], sfin[2];

    int bid = blockIdx.x, tid = threadIdx.x;

    for (int c = 0; c < CC; c++) {
        const float4* p = (const float4*)(X + (size_t)c * NPIX);

        // ---------------- Phase A: init + masked min/max partials ----------
        {
            int j = bid * 256 + tid;
            if (j < QH * QH * BINS) ((int*)&g_qh[c][0][0][0])[j] = 0;
            if (j == 0) {
                g_vmin2[c] = 0x7F800000;
                g_vmax2[c] = (int)0xFF800000;
                g_nm[c] = 0u;
            }
        }
        float vmin = F_INF, vmax = F_NINF;
        {
            int i0 = bid * 256 + tid;
            #pragma unroll 4
            for (int it = 0; it < 32; ++it) {
                float4 v = p[i0 + it * (NBLK * 256)];
                if (v.x > 0.f) { vmin = fminf(vmin, v.x); vmax = fmaxf(vmax, v.x); }
                if (v.y > 0.f) { vmin = fminf(vmin, v.y); vmax = fmaxf(vmax, v.y); }
                if (v.z > 0.f) { vmin = fminf(vmin, v.z); vmax = fmaxf(vmax, v.z); }
                if (v.w > 0.f) { vmin = fminf(vmin, v.w); vmax = fmaxf(vmax, v.w); }
            }
            #pragma unroll
            for (int o = 16; o; o >>= 1) {
                vmin = fminf(vmin, __shfl_down_sync(0xffffffffu, vmin, o));
                vmax = fmaxf(vmax, __shfl_down_sync(0xffffffffu, vmax, o));
            }
            if ((tid & 31) == 0) { smn[tid >> 5] = vmin; smx[tid >> 5] = vmax; }
            __syncthreads();
            if (tid == 0) {
                float a = F_INF, b = F_NINF;
                #pragma unroll
                for (int j = 0; j < 8; j++) { a = fminf(a, smn[j]); b = fmaxf(b, smx[j]); }
                g_part[bid] = make_float2(a, b);
            }
        }
        gbar();

        // ---------------- Phase B: quantize-histogram (X from L2) ----------
        vmin = F_INF; vmax = F_NINF;
        for (int j = tid; j < NBLK; j += 256) {
            float2 pp = g_part[j];
            vmin = fminf(vmin, pp.x); vmax = fmaxf(vmax, pp.y);
        }
        #pragma unroll
        for (int o = 16; o; o >>= 1) {
            vmin = fminf(vmin, __shfl_down_sync(0xffffffffu, vmin, o));
            vmax = fmaxf(vmax, __shfl_down_sync(0xffffffffu, vmax, o));
        }
        if ((tid & 31) == 0) { smn[tid >> 5] = vmin; smx[tid >> 5] = vmax; }
        for (int j = tid; j < QH * BINS; j += 256) sh[j] = 0;
        __syncthreads();
        if (tid == 0) {
            float a = F_INF, b = F_NINF;
            #pragma unroll
            for (int j = 0; j < 8; j++) { a = fminf(a, smn[j]); b = fmaxf(b, smx[j]); }
            sfin[0] = a; sfin[1] = b;
        }
        __syncthreads();
        float cvmin = sfin[0], cvmax = sfin[1];
        bool  cond = cvmax > 0.0f;
        float rng  = fmaxf(cvmax - cvmin, 1e-12f);
        float qa = cond ? (255.0f / rng) : 0.0f;           // kept live into phase D
        float qb = cond ? (-cvmin * qa) : 0.0f;

        {
            int base = bid * 8192;                         // 8 rows of 1024 float4
            unsigned int nm = 0;
            #pragma unroll 4
            for (int it = 0; it < 32; ++it) {
                int i = base + it * 256 + tid;
                float4 v = p[i];
                int tx = (i & 1023) >> 6;                  // 64 float4 per 256-px half
                float xs[4] = {v.x, v.y, v.z, v.w};
                #pragma unroll
                for (int k = 0; k < 4; k++) {
                    float x = xs[k];
                    bool  m = x > 0.0f;
                    float t = m ? fmaf(x, qa, qb) : 0.0f;
                    float fb = fminf(fmaxf(floorf(t), 0.0f), 255.0f);
                    atomicAdd(&sh[tx * BINS + (int)fb], 1);
                    nm += m ? 1u : 0u;
                }
            }
            __syncthreads();
            int yh = bid >> 5;                             // 32 blocks per 256-row half
            int* gq = &g_qh[c][yh][0][0];
            for (int j = tid; j < QH * BINS; j += 256) {
                int v = sh[j];
                if (v) atomicAdd(&gq[j], v);
            }
            #pragma unroll
            for (int o = 16; o; o >>= 1) nm += __shfl_down_sync(0xffffffffu, nm, o);
            if ((tid & 31) == 0) atomicAdd(&g_nm[c], nm);
        }
        gbar();

        // ---------------- Phase C1: stats + clip + redistribute + CDF LUT --
        if (bid < TT * TT) {
            int tile = bid, t = tid;
            const int* Q = &g_qh[c][0][0][0];
            unsigned int colsum = 0;
            #pragma unroll 8
            for (int k = 0; k < QH * QH; k++) colsum += (unsigned int)Q[k * BINS + t];
            sa[t] = t ? colsum : 0u;
            sb[t] = (unsigned int)t * colsum;
            __syncthreads();
            #pragma unroll
            for (int o = 128; o; o >>= 1) {
                if (t < o) { sa[t] += sa[t + o]; sb[t] += sb[t + o]; }
                __syncthreads();
            }
            unsigned int nz = sa[0], sum = sb[0];

            if (tile == 0 && t == 0) {
                unsigned int unmasked = (unsigned int)NPIX - g_nm[c];
                if (colsum > unmasked) { g_vmin2[c] = 0; g_vmax2[c] = 0; }
            }
            int mean = nz ? (int)(sum / nz) : 0;

            int ty = tile >> 3, tx = tile & 7;
            int q00 = ((2 * ty) * QH + 2 * tx) * BINS;
            int q01 = q00 + BINS;
            int q10 = q00 + QH * BINS;
            int q11 = q10 + BINS;
            int h  = Q[q00 + t] + Q[q01 + t] + Q[q10 + t] + Q[q11 + t];
            if (nz && mean != 0) {
                int h0 = Q[q00] + Q[q01] + Q[q10] + Q[q11];
                if (t == mean) h += h0;
                if (t == 0)    h  = 0;
            }

            int exc = max(h - CLV, 0);
            ssc[t] = exc; __syncthreads();
            #pragma unroll
            for (int o = 128; o; o >>= 1) { if (t < o) ssc[t] += ssc[t + o]; __syncthreads(); }
            int excess = ssc[0];
            __syncthreads();

            h = min(h, CLV);
            int batch = excess >> 8;
            int resid = excess & 255;
            int step  = 256 / max(resid, 1);
            h += batch + (((t % step) == 0 && (t / step) < resid) ? 1 : 0);

            ssc[t] = h; __syncthreads();
            #pragma unroll
            for (int o = 1; o < 256; o <<= 1) {
                int v = (t >= o) ? ssc[t - o] : 0;
                __syncthreads();
                ssc[t] += v;
                __syncthreads();
            }
            float lut = rintf((float)ssc[t] * (255.0f / (float)AREA));
            lut = fminf(fmaxf(lut, 0.0f), 255.0f);
            g_lut[c][tile][t] = (unsigned char)lut;
        }
        gbar();

        // ---------------- Phase C2: analytic y min/max over 9x9 regions ----
        if (bid >= 64 && bid < 64 + 81) {
            int reg = bid - 64, t = tid;
            int ry = reg / 9, rx = reg % 9;
            int rlo = (ry == 0) ? 0 : 512 * ry - 256;
            int rhi = (ry == 8) ? (HH - 1) : 512 * ry + 255;
            int clo = (rx == 0) ? 0 : 512 * rx - 256;
            int chi = (rx == 8) ? (WW - 1) : 512 * rx + 255;

            bool pres = false;
            if (t > 0) {
                int yh0 = rlo >> 8, yh1 = rhi >> 8;
                int xh0 = clo >> 8, xh1 = chi >> 8;
                for (int yh = yh0; yh <= yh1; ++yh)
                    for (int xh = xh0; xh <= xh1; ++xh)
                        pres |= (g_qh[c][yh][xh][t] > 0);
            }

            float lmin = F_INF, lmax = F_NINF;
            if (pres) {
                int y0 = max(ry - 1, 0); int y1 = min(y0 + 1, TT - 1);
                int xa = max(rx - 1, 0); int xb = min(xa + 1, TT - 1);
                const unsigned char* L = &g_lut[c][0][0];
                float a0 = (float)L[(y0 * TT + xa) * BINS + t];
                float da = (float)L[(y0 * TT + xb) * BINS + t] - a0;
                float b0 = (float)L[(y1 * TT + xa) * BINS + t];
                float db = (float)L[(y1 * TT + xb) * BINS + t] - b0;

                float fyl = ((float)rlo + 0.5f) * (1.0f / (float)THW) - 0.5f;
                float fyh = ((float)rhi + 0.5f) * (1.0f / (float)THW) - 0.5f;
                float wyv[2] = { fyl - floorf(fyl), fyh - floorf(fyh) };
                float fxl = ((float)clo + 0.5f) * (1.0f / (float)THW) - 0.5f;
                float fxh = ((float)chi + 0.5f) * (1.0f / (float)THW) - 0.5f;
                float wxv2[2] = { fxl - floorf(fxl), fxh - floorf(fxh) };

                #pragma unroll
                for (int jy = 0; jy < 2; jy++)
                    #pragma unroll
                    for (int jx = 0; jx < 2; jx++) {
                        float px = fmaf(wxv2[jx], da, a0);
                        float qx = fmaf(wxv2[jx], db, b0);
                        float eq = fmaf(wyv[jy], qx - px, px);
                        lmin = fminf(lmin, eq);
                        lmax = fmaxf(lmax, eq);
                    }
            }
            #pragma unroll
            for (int o = 16; o; o >>= 1) {
                lmin = fminf(lmin, __shfl_down_sync(0xffffffffu, lmin, o));
                lmax = fmaxf(lmax, __shfl_down_sync(0xffffffffu, lmax, o));
            }
            if ((t & 31) == 0) { smn[t >> 5] = lmin; smx[t >> 5] = lmax; }
            __syncthreads();
            if (t == 0) {
                float a = F_INF, b = F_NINF;
                #pragma unroll
                for (int j = 0; j < 8; j++) { a = fminf(a, smn[j]); b = fmaxf(b, smx[j]); }
                if (b != F_NINF) {
                    a = a * (1.0f / 255.0f);
                    b = b * (1.0f / 255.0f);
                    atomicMin(&g_vmin2[c], __float_as_int(a));
                    atomicMax(&g_vmax2[c], __float_as_int(b));
                }
            }
        }
        gbar();

        // ---------------- Phase D: apply (recompute bins from X in L2) -----
        {
            int r0 = bid * SROWS;
            float fy0 = ((float)r0 + 0.5f) * (1.0f / (float)THW) - 0.5f;
            int y0 = min(max((int)floorf(fy0), 0), TT - 1);
            int y1 = min(y0 + 1, TT - 1);

            const unsigned char* L = &g_lut[c][0][0];
            #pragma unroll
            for (int e0 = 0; e0 < 9 * BINS; e0 += 256) {
                int e = e0 + tid;
                int ix = e >> 8, f = e & 255;
                int xa = max(ix - 1, 0);
                int xb = min(xa + 1, TT - 1);
                if (f == 0) {
                    lutP[e] = make_uint2(0u, 0u);      // eq exactly 0 for bin 0
                } else {
                    float a0 = (float)L[(y0 * TT + xa) * BINS + f];
                    float a1 = (float)L[(y0 * TT + xb) * BINS + f];
                    float b0 = (float)L[(y1 * TT + xa) * BINS + f];
                    float b1 = (float)L[(y1 * TT + xb) * BINS + f];
                    lutP[e] = make_uint2(packbf(a0, a1 - a0), packbf(b0, b1 - b0));
                }
            }
            __syncthreads();

            float K1 = 0.0f, K2 = 0.0039215686f;
            {
                float vmax2 = __int_as_float(g_vmax2[c]);
                float vmin2 = __int_as_float(g_vmin2[c]);
                if (vmax2 > 0.0f) {
                    float rng2 = fmaxf(vmax2 - vmin2, 1e-12f);
                    float k1 = 0.99607843137f / rng2;
                    K1 = k1 * (1.0f / 255.0f);
                    K2 = 0.0039215686f - vmin2 * k1;
                }
            }

            float fx0 = ((float)(tid * 16) + 0.5f) * (1.0f / (float)THW) - 0.5f;
            float ffx = floorf(fx0);
            float wx0 = fx0 - ffx;
            const uint2* rowL = lutP + ((int)ffx + 1) * BINS;
            float wxv[16];
            #pragma unroll
            for (int j = 0; j < 16; j++) wxv[j] = fmaf((float)j, 1.0f / (float)THW, wx0);

            for (int rr = 0; rr < SROWS; ++rr) {
                int row = r0 + rr;
                float fyr = ((float)row + 0.5f) * (1.0f / (float)THW) - 0.5f;
                float wy = fyr - floorf(fyr);
                size_t rb4 = ((size_t)c * NPIX + (size_t)row * WW) >> 2;   // float4 units

                #pragma unroll
                for (int w = 0; w < 4; w++) {
                    float4 xv = p[(size_t)row * (WW / 4) + tid * 4 + w];
                    float xs[4] = {xv.x, xv.y, xv.z, xv.w};
                    float res[4];
                    #pragma unroll
                    for (int k = 0; k < 4; k++) {
                        float x = xs[k];
                        bool  m = x > 0.0f;
                        float t = m ? fmaf(x, qa, qb) : 0.0f;
                        float fb = fminf(fmaxf(floorf(t), 0.0f), 255.0f);
                        uint2 e = rowL[(int)fb];
                        float a0 = __int_as_float(e.x << 16);
                        float da = __int_as_float(e.x & 0xFFFF0000u);
                        float b0 = __int_as_float(e.y << 16);
                        float db = __int_as_float(e.y & 0xFFFF0000u);
                        float wx = wxv[w * 4 + k];
                        float px = fmaf(wx, da, a0);
                        float qx = fmaf(wx, db, b0);
                        float eq = fmaf(wy, qx - px, px);
                        float sc = fmaf(eq, K1, K2);
                        res[k] = m ? sc : 0.0f;
                    }
                    float4 o4; o4.x = res[0]; o4.y = res[1]; o4.z = res[2]; o4.w = res[3];
                    __stcs(((float4*)out) + rb4 + tid * 4 + w, o4);   // FIXED: rb4, not rb4/4
                }
            }
        }
        // no barrier: next channel's phase A touches disjoint state,
        // its closing barrier synchronizes everyone.
    }
}

// ========================= FALLBACK (proven R7) path =========================
__global__ void k_minmax(const float* __restrict__ X) {
    int c = blockIdx.y, bx = blockIdx.x, tid = threadIdx.x;
    if (tid < 64) ((int*)&g_qh[c][0][0][0])[bx * 64 + tid] = 0;
    if (bx == 0 && tid == 0) {
        g_vmin2[c] = 0x7F800000;
        g_vmax2[c] = (int)0xFF800000;
        g_nm[c] = 0u;
    }
    const float4* p = (const float4*)(X + (size_t)c * NPIX);
    int base = bx * 4096;
    float vmin = F_INF, vmax = F_NINF;
    #pragma unroll 4
    for (int it = 0; it < 16; ++it) {
        float4 v = p[base + it * 256 + tid];
        if (v.x > 0.f) { vmin = fminf(vmin, v.x); vmax = fmaxf(vmax, v.x); }
        if (v.y > 0.f) { vmin = fminf(vmin, v.y); vmax = fmaxf(vmax, v.y); }
        if (v.z > 0.f) { vmin = fminf(vmin, v.z); vmax = fmaxf(vmax, v.z); }
        if (v.w > 0.f) { vmin = fminf(vmin, v.w); vmax = fmaxf(vmax, v.w); }
    }
    __shared__ float smn[8], smx[8];
    #pragma unroll
    for (int o = 16; o; o >>= 1) {
        vmin = fminf(vmin, __shfl_down_sync(0xffffffffu, vmin, o));
        vmax = fmaxf(vmax, __shfl_down_sync(0xffffffffu, vmax, o));
    }
    if ((tid & 31) == 0) { smn[tid >> 5] = vmin; smx[tid >> 5] = vmax; }
    __syncthreads();
    if (tid == 0) {
        float a = F_INF, b = F_NINF;
        #pragma unroll
        for (int j = 0; j < 8; j++) { a = fminf(a, smn[j]); b = fmaxf(b, smx[j]); }
        g_part[c * MMB + bx] = make_float2(a, b);
    }
}

__global__ void k_quant(const float* __restrict__ X) {
    int c = blockIdx.y, bx = blockIdx.x, tid = threadIdx.x;
    __shared__ int sh[QH * BINS];
    __shared__ float smn[8], smx[8], sfin[2];
    float vmin = F_INF, vmax = F_NINF;
    for (int j = tid; j < MMB; j += 256) {
        float2 pp = g_part[c * MMB + j];
        vmin = fminf(vmin, pp.x); vmax = fmaxf(vmax, pp.y);
    }
    #pragma unroll
    for (int o = 16; o; o >>= 1) {
        vmin = fminf(vmin, __shfl_down_sync(0xffffffffu, vmin, o));
        vmax = fmaxf(vmax, __shfl_down_sync(0xffffffffu, vmax, o));
    }
    if ((tid & 31) == 0) { smn[tid >> 5] = vmin; smx[tid >> 5] = vmax; }
    for (int j = tid; j < QH * BINS; j += 256) sh[j] = 0;
    __syncthreads();
    if (tid == 0) {
        float a = F_INF, b = F_NINF;
        #pragma unroll
        for (int j = 0; j < 8; j++) { a = fminf(a, smn[j]); b = fmaxf(b, smx[j]); }
        sfin[0] = a; sfin[1] = b;
    }
    __syncthreads();
    vmin = sfin[0]; vmax = sfin[1];
    bool  cond = vmax > 0.0f;
    float rng  = fmaxf(vmax - vmin, 1e-12f);
    float a255 = cond ? (255.0f / rng) : 0.0f;
    float b255 = cond ? (-vmin * a255) : 0.0f;
    const float4* p  = (const float4*)(X + (size_t)c * NPIX);
    uchar4*       q8 = (uchar4*)(g_q + (size_t)c * NPIX);
    unsigned char* mp = g_m + (size_t)c * (NPIX / 4);
    int base = bx * 8192;
    unsigned int nm = 0;
    #pragma unroll 4
    for (int it = 0; it < 32; ++it) {
        int i = base + it * 256 + tid;
        float4 v = p[i];
        int tx = (i & 1023) >> 6;
        float xs[4] = {v.x, v.y, v.z, v.w};
        unsigned char r[4]; unsigned int nib = 0;
        #pragma unroll
        for (int k = 0; k < 4; k++) {
            float x = xs[k];
            bool  m = x > 0.0f;
            float t = m ? fmaf(x, a255, b255) : 0.0f;
            float fb = fminf(fmaxf(floorf(t), 0.0f), 255.0f);
            int b = (int)fb;
            atomicAdd(&sh[tx * BINS + b], 1);
            r[k] = (unsigned char)b;
            nib |= (m ? 1u : 0u) << k;
        }
        nm += (unsigned int)__popc(nib);
        uchar4 o; o.x = r[0]; o.y = r[1]; o.z = r[2]; o.w = r[3];
        q8[i] = o;
        mp[i] = (unsigned char)nib;
    }
    __syncthreads();
    int yh = bx >> 5;
    int* gq = &g_qh[c][yh][0][0];
    for (int j = tid; j < QH * BINS; j += 256) {
        int v = sh[j];
        if (v) atomicAdd(&gq[j], v);
    }
    #pragma unroll
    for (int o = 16; o; o >>= 1) nm += __shfl_down_sync(0xffffffffu, nm, o);
    if ((tid & 31) == 0) atomicAdd(&g_nm[c], nm);
}

__global__ void k_lut() {
    int c = blockIdx.y, tile = blockIdx.x, t = threadIdx.x;
    __shared__ unsigned int sa[BINS], sb[BINS];
    __shared__ int s[BINS];
    const int* Q = &g_qh[c][0][0][0];
    unsigned int colsum = 0;
    #pragma unroll 8
    for (int k = 0; k < QH * QH; k++) colsum += (unsigned int)Q[k * BINS + t];
    sa[t] = t ? colsum : 0u;
    sb[t] = (unsigned int)t * colsum;
    __syncthreads();
    #pragma unroll
    for (int o = 128; o; o >>= 1) {
        if (t < o) { sa[t] += sa[t + o]; sb[t] += sb[t + o]; }
        __syncthreads();
    }
    unsigned int nz = sa[0], sum = sb[0];
    if (tile == 0 && t == 0) {
        unsigned int unmasked = (unsigned int)NPIX - g_nm[c];
        if (colsum > unmasked) { g_vmin2[c] = 0; g_vmax2[c] = 0; }
    }
    int mean = nz ? (int)(sum / nz) : 0;
    int ty = tile >> 3, tx = tile & 7;
    int q00 = ((2 * ty) * QH + 2 * tx) * BINS;
    int q01 = q00 + BINS;
    int q10 = q00 + QH * BINS;
    int q11 = q10 + BINS;
    int h  = Q[q00 + t] + Q[q01 + t] + Q[q10 + t] + Q[q11 + t];
    if (nz && mean != 0) {
        int h0 = Q[q00] + Q[q01] + Q[q10] + Q[q11];
        if (t == mean) h += h0;
        if (t == 0)    h  = 0;
    }
    int exc = max(h - CLV, 0);
    s[t] = exc; __syncthreads();
    #pragma unroll
    for (int o = 128; o; o >>= 1) { if (t < o) s[t] += s[t + o]; __syncthreads(); }
    int excess = s[0];
    __syncthreads();
    h = min(h, CLV);
    int batch = excess >> 8;
    int resid = excess & 255;
    int step  = 256 / max(resid, 1);
    h += batch + (((t % step) == 0 && (t / step) < resid) ? 1 : 0);
    s[t] = h; __syncthreads();
    #pragma unroll
    for (int o = 1; o < 256; o <<= 1) {
        int v = (t >= o) ? s[t - o] : 0;
        __syncthreads();
        s[t] += v;
        __syncthreads();
    }
    float lut = rintf((float)s[t] * (255.0f / (float)AREA));
    lut = fminf(fmaxf(lut, 0.0f), 255.0f);
    g_lut[c][tile][t] = (unsigned char)lut;
}

__global__ void k_mm2() {
    int c = blockIdx.y, reg = blockIdx.x, t = threadIdx.x;
    int ry = reg / 9, rx = reg % 9;
    int rlo = (ry == 0) ? 0 : 512 * ry - 256;
    int rhi = (ry == 8) ? (HH - 1) : 512 * ry + 255;
    int clo = (rx == 0) ? 0 : 512 * rx - 256;
    int chi = (rx == 8) ? (WW - 1) : 512 * rx + 255;
    bool pres = false;
    if (t > 0) {
        int yh0 = rlo >> 8, yh1 = rhi >> 8;
        int xh0 = clo >> 8, xh1 = chi >> 8;
        for (int yh = yh0; yh <= yh1; ++yh)
            for (int xh = xh0; xh <= xh1; ++xh)
                pres |= (g_qh[c][yh][xh][t] > 0);
    }
    float lmin = F_INF, lmax = F_NINF;
    if (pres) {
        int y0 = max(ry - 1, 0); int y1 = min(y0 + 1, TT - 1);
        int xa = max(rx - 1, 0); int xb = min(xa + 1, TT - 1);
        const unsigned char* L = &g_lut[c][0][0];
        float a0 = (float)L[(y0 * TT + xa) * BINS + t];
        float da = (float)L[(y0 * TT + xb) * BINS + t] - a0;
        float b0 = (float)L[(y1 * TT + xa) * BINS + t];
        float db = (float)L[(y1 * TT + xb) * BINS + t] - b0;
        float fyl = ((float)rlo + 0.5f) * (1.0f / (float)THW) - 0.5f;
        float fyh = ((float)rhi + 0.5f) * (1.0f / (float)THW) - 0.5f;
        float wyv[2] = { fyl - floorf(fyl), fyh - floorf(fyh) };
        float fxl = ((float)clo + 0.5f) * (1.0f / (float)THW) - 0.5f;
        float fxh = ((float)chi + 0.5f) * (1.0f / (float)THW) - 0.5f;
        float wxv[2] = { fxl - floorf(fxl), fxh - floorf(fxh) };
        #pragma unroll
        for (int jy = 0; jy < 2; jy++)
            #pragma unroll
            for (int jx = 0; jx < 2; jx++) {
                float px = fmaf(wxv[jx], da, a0);
                float qx = fmaf(wxv[jx], db, b0);
                float eq = fmaf(wyv[jy], qx - px, px);
                lmin = fminf(lmin, eq);
                lmax = fmaxf(lmax, eq);
            }
    }
    __shared__ float smn[8], smx[8];
    #pragma unroll
    for (int o = 16; o; o >>= 1) {
        lmin = fminf(lmin, __shfl_down_sync(0xffffffffu, lmin, o));
        lmax = fmaxf(lmax, __shfl_down_sync(0xffffffffu, lmax, o));
    }
    if ((t & 31) == 0) { smn[t >> 5] = lmin; smx[t >> 5] = lmax; }
    __syncthreads();
    if (t == 0) {
        float a = F_INF, b = F_NINF;
        #pragma unroll
        for (int j = 0; j < 8; j++) { a = fminf(a, smn[j]); b = fmaxf(b, smx[j]); }
        if (b != F_NINF) {
            a = a * (1.0f / 255.0f);
            b = b * (1.0f / 255.0f);
            atomicMin(&g_vmin2[c], __float_as_int(a));
            atomicMax(&g_vmax2[c], __float_as_int(b));
        }
    }
}

__global__ void __launch_bounds__(256) k_apply(float* __restrict__ out) {
    int c = blockIdx.y, s = blockIdx.x, tid = threadIdx.x;
    int r0 = s * SROWS;
    __shared__ uint2 lutP[9 * BINS];
    float fy0 = ((float)r0 + 0.5f) * (1.0f / (float)THW) - 0.5f;
    int y0 = min(max((int)floorf(fy0), 0), TT - 1);
    int y1 = min(y0 + 1, TT - 1);
    const unsigned char* L = &g_lut[c][0][0];
    #pragma unroll
    for (int e0 = 0; e0 < 9 * BINS; e0 += 256) {
        int e = e0 + tid;
        int ix = e >> 8, f = e & 255;
        int xa = max(ix - 1, 0);
        int xb = min(xa + 1, TT - 1);
        if (f == 0) {
            lutP[e] = make_uint2(0u, 0u);
        } else {
            float a0 = (float)L[(y0 * TT + xa) * BINS + f];
            float a1 = (float)L[(y0 * TT + xb) * BINS + f];
            float b0 = (float)L[(y1 * TT + xa) * BINS + f];
            float b1 = (float)L[(y1 * TT + xb) * BINS + f];
            lutP[e] = make_uint2(packbf(a0, a1 - a0), packbf(b0, b1 - b0));
        }
    }
    __syncthreads();
    float K1 = 0.0f, K2 = 0.0039215686f;
    {
        float vmax2 = __int_as_float(g_vmax2[c]);
        float vmin2 = __int_as_float(g_vmin2[c]);
        if (vmax2 > 0.0f) {
            float rng2 = fmaxf(vmax2 - vmin2, 1e-12f);
            float k1 = 0.99607843137f / rng2;
            K1 = k1 * (1.0f / 255.0f);
            K2 = 0.0039215686f - vmin2 * k1;
        }
    }
    float fx0 = ((float)(tid * 16) + 0.5f) * (1.0f / (float)THW) - 0.5f;
    float ffx = floorf(fx0);
    float wx0 = fx0 - ffx;
    const uint2* rowL = lutP + ((int)ffx + 1) * BINS;
    float wxv[16];
    #pragma unroll
    for (int j = 0; j < 16; j++) wxv[j] = fmaf((float)j, 1.0f / (float)THW, wx0);
    int rowstride = WW / 16;
    size_t base16 = ((size_t)c * NPIX + (size_t)r0 * WW) >> 4;
    const uint4* qp = ((const uint4*)g_q) + base16 + tid;
    const unsigned int* mp = ((const unsigned int*)g_m) + base16 + tid;
    float4* op = ((float4*)out) + (((size_t)c * NPIX + (size_t)r0 * WW) >> 2) + tid * 4;
    for (int rr = 0; rr < SROWS; ++rr) {
        float fyr = ((float)(r0 + rr) + 0.5f) * (1.0f / (float)THW) - 0.5f;
        float wy = fyr - floorf(fyr);
        uint4 qw = qp[rr * rowstride];
        unsigned int mw = mp[rr * rowstride];
        unsigned int wv[4] = {qw.x, qw.y, qw.z, qw.w};
        #pragma unroll
        for (int w = 0; w < 4; w++) {
            float res[4];
            #pragma unroll
            for (int k = 0; k < 4; k++) {
                unsigned int v = (wv[w] >> (8 * k)) & 255u;
                uint2 e = rowL[v];
                float a0 = __int_as_float(e.x << 16);
                float da = __int_as_float(e.x & 0xFFFF0000u);
                float b0 = __int_as_float(e.y << 16);
                float db = __int_as_float(e.y & 0xFFFF0000u);
                float wx = wxv[w * 4 + k];
                float px = fmaf(wx, da, a0);
                float qx = fmaf(wx, db, b0);
                float eq = fmaf(wy, qx - px, px);
                float sc = fmaf(eq, K1, K2);
                res[k] = ((mw >> (8 * w + k)) & 1u) ? sc : 0.0f;
            }
            float4 o4; o4.x = res[0]; o4.y = res[1]; o4.z = res[2]; o4.w = res[3];
            op[(size_t)rr * (WW / 4) + w] = o4;
        }
    }
}

// ---------------------------------------------------------------------------
extern "C" void kernel_launch(void* const* d_in, const int* in_sizes, int n_in,
                              void* d_out, int out_size) {
    const float* X = (const float*)d_in[0];
    float* out = (float*)d_out;

    // deadlock safety: the persistent kernel requires all NBLK blocks resident.
    static int can_fuse = -1;
    if (can_fuse < 0) {
        int nb = 0;
        cudaOccupancyMaxActiveBlocksPerMultiprocessor(&nb, k_fused, 256, 0);
        int dev = 0, sms = 0;
        cudaGetDevice(&dev);
        cudaDeviceGetAttribute(&sms, cudaDevAttrMultiProcessorCount, dev);
        can_fuse = ((long long)nb * sms >= NBLK) ? 1 : 0;
    }

    if (can_fuse) {
        k_fused<<<NBLK, 256>>>(X, out);
    } else {
        dim3 g1(MMB, CC);        k_minmax<<<g1, 256>>>(X);
        dim3 g2(512, CC);        k_quant <<<g2, 256>>>(X);
        dim3 g3(TT*TT, CC);      k_lut   <<<g3, 256>>>();
        dim3 g5(81, CC);         k_mm2   <<<g5, 256>>>();
        dim3 g4(HH/SROWS, CC);   k_apply <<<g4, 256>>>(out);
    }
}

// round 10
// speedup vs baseline: 1.4563x; 1.4563x over previous
#include <cuda_runtime.h>
#include <cstdint>

#define CC   4
#define HH   4096
#define WW   4096
#define NPIX (HH*WW)          // per-channel pixels: 16777216
#define TT   8
#define THW  512
#define BINS 256
#define AREA (THW*THW)        // 262144
#define CLV  40960            // int(40.0 * AREA / BINS)
#define MMB  512              // minmax partial blocks per channel
#define SROWS 8               // rows per apply strip
#define QH   16               // 256-px halves per dim
#define QBLK 512              // quant blocks per channel (8 rows each)

// ---------------- scratch (static device globals; no allocation) ------------
__device__ unsigned char      g_q[(size_t)CC * NPIX];        // quantized value 0..255
__device__ unsigned char      g_m[(size_t)CC * NPIX / 4];    // mask nibble per float4 group
__device__ int                g_qh[CC][QH][QH][BINS];        // quadrant histograms
__device__ unsigned char      g_lut[CC][TT*TT][BINS];
__device__ float2             g_part[CC * MMB];              // per-block (min,max) partials
__device__ int                g_vmin2[CC], g_vmax2[CC];      // float bits (y>=0 -> int trick)
__device__ unsigned int       g_nm[CC];                      // masked-pixel count

#define F_INF  __int_as_float(0x7F800000)
#define F_NINF __int_as_float((int)0xFF800000)

__device__ __forceinline__ unsigned int packbf(float lo, float hi) {
    return (__float_as_uint(lo) >> 16) | (__float_as_uint(hi) & 0xFFFF0000u);
}

// ===== heterogeneous step: blocks [0,QBLK) quantize channel cq,
// ===== blocks [QBLK, QBLK+MMB) do init+minmax partials for channel cm.
// ===== Kernel boundaries provide all cross-phase synchronization.
__global__ void __launch_bounds__(256) k_step(const float* __restrict__ X,
                                              int cq, int cm) {
    __shared__ int sh[QH * BINS];                 // 16 KB (quant role)
    __shared__ float smn[8], smx[8], sfin[2];

    int tid = threadIdx.x;

    if (blockIdx.x >= QBLK) {
        // ---------------- minmax role: channel cm ---------------------------
        if (cm < 0) return;
        int b = blockIdx.x - QBLK;

        // init: zero quadrant hists (65536 ints / 512 blocks = 128 each) + scalars
        if (tid < 128) ((int*)&g_qh[cm][0][0][0])[b * 128 + tid] = 0;
        if (b == 0 && tid == 0) {
            g_vmin2[cm] = 0x7F800000;
            g_vmax2[cm] = (int)0xFF800000;
            g_nm[cm] = 0u;
        }

        const float4* p = (const float4*)(X + (size_t)cm * NPIX);
        int base = b * 8192;                      // 8192 float4 per block
        float vmin = F_INF, vmax = F_NINF;
        #pragma unroll 4
        for (int it = 0; it < 32; ++it) {
            float4 v = p[base + it * 256 + tid];
            if (v.x > 0.f) { vmin = fminf(vmin, v.x); vmax = fmaxf(vmax, v.x); }
            if (v.y > 0.f) { vmin = fminf(vmin, v.y); vmax = fmaxf(vmax, v.y); }
            if (v.z > 0.f) { vmin = fminf(vmin, v.z); vmax = fmaxf(vmax, v.z); }
            if (v.w > 0.f) { vmin = fminf(vmin, v.w); vmax = fmaxf(vmax, v.w); }
        }
        #pragma unroll
        for (int o = 16; o; o >>= 1) {
            vmin = fminf(vmin, __shfl_down_sync(0xffffffffu, vmin, o));
            vmax = fmaxf(vmax, __shfl_down_sync(0xffffffffu, vmax, o));
        }
        if ((tid & 31) == 0) { smn[tid >> 5] = vmin; smx[tid >> 5] = vmax; }
        __syncthreads();
        if (tid == 0) {
            float a = F_INF, bb = F_NINF;
            #pragma unroll
            for (int j = 0; j < 8; j++) { a = fminf(a, smn[j]); bb = fmaxf(bb, smx[j]); }
            g_part[cm * MMB + b] = make_float2(a, bb);
        }
        return;
    }

    // ---------------- quant role: channel cq (partials from previous launch) -
    if (cq < 0) return;
    int bx = blockIdx.x;

    float vmin = F_INF, vmax = F_NINF;
    for (int j = tid; j < MMB; j += 256) {
        float2 pp = g_part[cq * MMB + j];
        vmin = fminf(vmin, pp.x); vmax = fmaxf(vmax, pp.y);
    }
    #pragma unroll
    for (int o = 16; o; o >>= 1) {
        vmin = fminf(vmin, __shfl_down_sync(0xffffffffu, vmin, o));
        vmax = fmaxf(vmax, __shfl_down_sync(0xffffffffu, vmax, o));
    }
    if ((tid & 31) == 0) { smn[tid >> 5] = vmin; smx[tid >> 5] = vmax; }
    for (int j = tid; j < QH * BINS; j += 256) sh[j] = 0;
    __syncthreads();
    if (tid == 0) {
        float a = F_INF, b = F_NINF;
        #pragma unroll
        for (int j = 0; j < 8; j++) { a = fminf(a, smn[j]); b = fmaxf(b, smx[j]); }
        sfin[0] = a; sfin[1] = b;
    }
    __syncthreads();
    vmin = sfin[0]; vmax = sfin[1];
    bool  cond = vmax > 0.0f;
    float rng  = fmaxf(vmax - vmin, 1e-12f);
    float a255 = cond ? (255.0f / rng) : 0.0f;
    float b255 = cond ? (-vmin * a255) : 0.0f;

    const float4* p  = (const float4*)(X + (size_t)cq * NPIX);
    uchar4*       q8 = (uchar4*)(g_q + (size_t)cq * NPIX);
    unsigned char* mp = g_m + (size_t)cq * (NPIX / 4);

    int base = bx * 8192;                         // 8 rows of 1024 float4
    unsigned int nm = 0;

    #pragma unroll 4
    for (int it = 0; it < 32; ++it) {
        int i = base + it * 256 + tid;
        float4 v = p[i];
        int tx = (i & 1023) >> 6;                 // 64 float4 per 256-px half
        float xs[4] = {v.x, v.y, v.z, v.w};
        unsigned char r[4]; unsigned int nib = 0;
        #pragma unroll
        for (int k = 0; k < 4; k++) {
            float x = xs[k];
            bool  m = x > 0.0f;
            float t = m ? fmaf(x, a255, b255) : 0.0f;
            float fb = fminf(fmaxf(floorf(t), 0.0f), 255.0f);
            int b = (int)fb;
            atomicAdd(&sh[tx * BINS + b], 1);
            r[k] = (unsigned char)b;
            nib |= (m ? 1u : 0u) << k;
        }
        nm += (unsigned int)__popc(nib);
        uchar4 o; o.x = r[0]; o.y = r[1]; o.z = r[2]; o.w = r[3];
        q8[i] = o;
        mp[i] = (unsigned char)nib;
    }
    __syncthreads();

    int yh = bx >> 5;                             // 32 blocks (8 rows) per 256-row half
    int* gq = &g_qh[cq][yh][0][0];
    for (int j = tid; j < QH * BINS; j += 256) {
        int v = sh[j];
        if (v) atomicAdd(&gq[j], v);
    }
    #pragma unroll
    for (int o = 16; o; o >>= 1) nm += __shfl_down_sync(0xffffffffu, nm, o);
    if ((tid & 31) == 0) atomicAdd(&g_nm[cq], nm);
}

// ------- stats from quadrant hists, clip + redistribute + CDF -> u8 LUT -----
__global__ void k_lut() {
    int c = blockIdx.y, tile = blockIdx.x, t = threadIdx.x;
    __shared__ unsigned int sa[BINS], sb[BINS];
    __shared__ int s[BINS];

    const int* Q = &g_qh[c][0][0][0];
    unsigned int colsum = 0;
    #pragma unroll 8
    for (int k = 0; k < QH * QH; k++) colsum += (unsigned int)Q[k * BINS + t];
    sa[t] = t ? colsum : 0u;                      // nz excludes bin 0
    sb[t] = (unsigned int)t * colsum;             // max 255*16.7M < 2^32
    __syncthreads();
    #pragma unroll
    for (int o = 128; o; o >>= 1) {
        if (t < o) { sa[t] += sa[t + o]; sb[t] += sb[t + o]; }
        __syncthreads();
    }
    unsigned int nz = sa[0], sum = sb[0];

    if (tile == 0 && t == 0) {
        // masked bin-0 pixel exists <=> bin0 total > unmasked count -> y=0 candidate
        unsigned int unmasked = (unsigned int)NPIX - g_nm[c];
        if (colsum > unmasked) { g_vmin2[c] = 0; g_vmax2[c] = 0; }
    }

    int mean = nz ? (int)(sum / nz) : 0;

    int ty = tile >> 3, tx = tile & 7;
    int q00 = ((2 * ty) * QH + 2 * tx) * BINS;
    int q01 = q00 + BINS;
    int q10 = q00 + QH * BINS;
    int q11 = q10 + BINS;
    int h  = Q[q00 + t] + Q[q01 + t] + Q[q10 + t] + Q[q11 + t];
    if (nz && mean != 0) {                        // hist of `filled`: move bin0 -> mean
        int h0 = Q[q00] + Q[q01] + Q[q10] + Q[q11];
        if (t == mean) h += h0;
        if (t == 0)    h  = 0;
    }

    int exc = max(h - CLV, 0);
    s[t] = exc; __syncthreads();
    #pragma unroll
    for (int o = 128; o; o >>= 1) { if (t < o) s[t] += s[t + o]; __syncthreads(); }
    int excess = s[0];
    __syncthreads();

    h = min(h, CLV);
    int batch = excess >> 8;
    int resid = excess & 255;
    int step  = 256 / max(resid, 1);
    h += batch + (((t % step) == 0 && (t / step) < resid) ? 1 : 0);

    s[t] = h; __syncthreads();
    #pragma unroll
    for (int o = 1; o < 256; o <<= 1) {
        int v = (t >= o) ? s[t - o] : 0;
        __syncthreads();
        s[t] += v;
        __syncthreads();
    }
    float lut = rintf((float)s[t] * (255.0f / (float)AREA));
    lut = fminf(fmaxf(lut, 0.0f), 255.0f);
    g_lut[c][tile][t] = (unsigned char)lut;
}

// ---- analytic pass-2 min/max: eq bilinear per (region, bin), extremes at
// ---- the 4 corner pixels of each 9x9 dual region. Exact. --------------------
__global__ void k_mm2() {
    int c = blockIdx.y, reg = blockIdx.x, t = threadIdx.x;
    int ry = reg / 9, rx = reg % 9;
    int rlo = (ry == 0) ? 0 : 512 * ry - 256;
    int rhi = (ry == 8) ? (HH - 1) : 512 * ry + 255;
    int clo = (rx == 0) ? 0 : 512 * rx - 256;
    int chi = (rx == 8) ? (WW - 1) : 512 * rx + 255;

    bool pres = false;
    if (t > 0) {
        int yh0 = rlo >> 8, yh1 = rhi >> 8;
        int xh0 = clo >> 8, xh1 = chi >> 8;
        for (int yh = yh0; yh <= yh1; ++yh)
            for (int xh = xh0; xh <= xh1; ++xh)
                pres |= (g_qh[c][yh][xh][t] > 0);
    }

    float lmin = F_INF, lmax = F_NINF;
    if (pres) {
        int y0 = max(ry - 1, 0); int y1 = min(y0 + 1, TT - 1);
        int xa = max(rx - 1, 0); int xb = min(xa + 1, TT - 1);
        const unsigned char* L = &g_lut[c][0][0];
        float a0 = (float)L[(y0 * TT + xa) * BINS + t];
        float da = (float)L[(y0 * TT + xb) * BINS + t] - a0;
        float b0 = (float)L[(y1 * TT + xa) * BINS + t];
        float db = (float)L[(y1 * TT + xb) * BINS + t] - b0;

        float fyl = ((float)rlo + 0.5f) * (1.0f / (float)THW) - 0.5f;
        float fyh = ((float)rhi + 0.5f) * (1.0f / (float)THW) - 0.5f;
        float wyv[2] = { fyl - floorf(fyl), fyh - floorf(fyh) };
        float fxl = ((float)clo + 0.5f) * (1.0f / (float)THW) - 0.5f;
        float fxh = ((float)chi + 0.5f) * (1.0f / (float)THW) - 0.5f;
        float wxv[2] = { fxl - floorf(fxl), fxh - floorf(fxh) };

        #pragma unroll
        for (int jy = 0; jy < 2; jy++)
            #pragma unroll
            for (int jx = 0; jx < 2; jx++) {
                float px = fmaf(wxv[jx], da, a0);
                float qx = fmaf(wxv[jx], db, b0);
                float eq = fmaf(wyv[jy], qx - px, px);
                lmin = fminf(lmin, eq);
                lmax = fmaxf(lmax, eq);
            }
    }

    __shared__ float smn[8], smx[8];
    #pragma unroll
    for (int o = 16; o; o >>= 1) {
        lmin = fminf(lmin, __shfl_down_sync(0xffffffffu, lmin, o));
        lmax = fmaxf(lmax, __shfl_down_sync(0xffffffffu, lmax, o));
    }
    if ((t & 31) == 0) { smn[t >> 5] = lmin; smx[t >> 5] = lmax; }
    __syncthreads();
    if (t == 0) {
        float a = F_INF, b = F_NINF;
        #pragma unroll
        for (int j = 0; j < 8; j++) { a = fminf(a, smn[j]); b = fmaxf(b, smx[j]); }
        if (b != F_NINF) {
            a = a * (1.0f / 255.0f);              // y = eq/255 (monotone)
            b = b * (1.0f / 255.0f);
            atomicMin(&g_vmin2[c], __float_as_int(a));
            atomicMax(&g_vmax2[c], __float_as_int(b));
        }
    }
}

// -------- apply: 8-row strips, bf16-packed strip LUT, final write -----------
__global__ void __launch_bounds__(256) k_apply(float* __restrict__ out) {
    int c = blockIdx.y, s = blockIdx.x, tid = threadIdx.x;
    int r0 = s * SROWS;
    __shared__ uint2 lutP[9 * BINS];              // 18 KB

    float fy0 = ((float)r0 + 0.5f) * (1.0f / (float)THW) - 0.5f;
    int y0 = min(max((int)floorf(fy0), 0), TT - 1);
    int y1 = min(y0 + 1, TT - 1);

    const unsigned char* L = &g_lut[c][0][0];
    #pragma unroll
    for (int e0 = 0; e0 < 9 * BINS; e0 += 256) {
        int e = e0 + tid;
        int ix = e >> 8, f = e & 255;
        int xa = max(ix - 1, 0);
        int xb = min(xa + 1, TT - 1);
        if (f == 0) {
            lutP[e] = make_uint2(0u, 0u);         // eq exactly 0 for bin 0
        } else {
            float a0 = (float)L[(y0 * TT + xa) * BINS + f];
            float a1 = (float)L[(y0 * TT + xb) * BINS + f];
            float b0 = (float)L[(y1 * TT + xa) * BINS + f];
            float b1 = (float)L[(y1 * TT + xb) * BINS + f];
            lutP[e] = make_uint2(packbf(a0, a1 - a0), packbf(b0, b1 - b0));
        }
    }
    __syncthreads();

    float K1 = 0.0f, K2 = 0.0039215686f;
    {
        float vmax2 = __int_as_float(g_vmax2[c]);
        float vmin2 = __int_as_float(g_vmin2[c]);
        if (vmax2 > 0.0f) {
            float rng2 = fmaxf(vmax2 - vmin2, 1e-12f);
            float k1 = 0.99607843137f / rng2;
            K1 = k1 * (1.0f / 255.0f);
            K2 = 0.0039215686f - vmin2 * k1;
        }
    }

    float fx0 = ((float)(tid * 16) + 0.5f) * (1.0f / (float)THW) - 0.5f;
    float ffx = floorf(fx0);
    float wx0 = fx0 - ffx;
    const uint2* rowL = lutP + ((int)ffx + 1) * BINS;
    float wxv[16];
    #pragma unroll
    for (int j = 0; j < 16; j++) wxv[j] = fmaf((float)j, 1.0f / (float)THW, wx0);

    int rowstride = WW / 16;
    size_t base16 = ((size_t)c * NPIX + (size_t)r0 * WW) >> 4;
    const uint4* qp = ((const uint4*)g_q) + base16 + tid;
    const unsigned int* mp = ((const unsigned int*)g_m) + base16 + tid;
    float4* op = ((float4*)out) + (((size_t)c * NPIX + (size_t)r0 * WW) >> 2) + tid * 4;

    for (int rr = 0; rr < SROWS; ++rr) {
        float fyr = ((float)(r0 + rr) + 0.5f) * (1.0f / (float)THW) - 0.5f;
        float wy = fyr - floorf(fyr);
        uint4 qw = qp[rr * rowstride];
        unsigned int mw = mp[rr * rowstride];
        unsigned int wv[4] = {qw.x, qw.y, qw.z, qw.w};
        #pragma unroll
        for (int w = 0; w < 4; w++) {
            float res[4];
            #pragma unroll
            for (int k = 0; k < 4; k++) {
                unsigned int v = (wv[w] >> (8 * k)) & 255u;
                uint2 e = rowL[v];
                float a0 = __int_as_float(e.x << 16);
                float da = __int_as_float(e.x & 0xFFFF0000u);
                float b0 = __int_as_float(e.y << 16);
                float db = __int_as_float(e.y & 0xFFFF0000u);
                float wx = wxv[w * 4 + k];
                float px = fmaf(wx, da, a0);
                float qx = fmaf(wx, db, b0);
                float eq = fmaf(wy, qx - px, px);
                float sc = fmaf(eq, K1, K2);
                res[k] = ((mw >> (8 * w + k)) & 1u) ? sc : 0.0f;
            }
            float4 o4; o4.x = res[0]; o4.y = res[1]; o4.z = res[2]; o4.w = res[3];
            op[(size_t)rr * (WW / 4) + w] = o4;
        }
    }
}

// ---------------------------------------------------------------------------
extern "C" void kernel_launch(void* const* d_in, const int* in_sizes, int n_in,
                              void* d_out, int out_size) {
    const float* X = (const float*)d_in[0];
    float* out = (float*)d_out;

    // software-pipelined: quant(c) overlaps minmax(c+1); kernel boundaries sync
    k_step<<<QBLK + MMB, 256>>>(X, -1, 0);
    k_step<<<QBLK + MMB, 256>>>(X,  0, 1);
    k_step<<<QBLK + MMB, 256>>>(X,  1, 2);
    k_step<<<QBLK + MMB, 256>>>(X,  2, 3);
    k_step<<<QBLK + MMB, 256>>>(X,  3, -1);

    dim3 g3(TT*TT, CC);      k_lut  <<<g3, 256>>>();
    dim3 g5(81, CC);         k_mm2  <<<g5, 256>>>();
    dim3 g4(HH/SROWS, CC);   k_apply<<<g4, 256>>>(out);
}

// round 11
// speedup vs baseline: 1.4721x; 1.0109x over previous
#include <cuda_runtime.h>
#include <cstdint>

#define CC   4
#define HH   4096
#define WW   4096
#define NPIX (HH*WW)          // per-channel pixels: 16777216
#define TT   8
#define THW  512
#define BINS 256
#define AREA (THW*THW)        // 262144
#define CLV  40960            // int(40.0 * AREA / BINS)
#define MMB  512              // minmax partial blocks per channel
#define SROWS 8               // rows per apply strip
#define QH   16               // 256-px halves per dim
#define QBLK 512              // quant blocks per channel (8 rows each)
#define NBLK 512              // cooperative grid size

// ---------------- scratch (static device globals; no allocation) ------------
__device__ unsigned char      g_q[(size_t)CC * NPIX];        // quantized value 0..255
__device__ unsigned char      g_m[(size_t)CC * NPIX / 4];    // mask nibble per float4 group
__device__ int                g_qh[CC][QH][QH][BINS];        // quadrant histograms
__device__ unsigned char      g_lut[CC][TT*TT][BINS];
__device__ float2             g_part[CC * MMB];              // per-block (min,max) partials
__device__ int                g_vmin2[CC], g_vmax2[CC];      // float bits (y>=0 -> int trick)
__device__ unsigned int       g_nm[CC];                      // masked-pixel count
__device__ unsigned int       g_barcnt = 0;                  // barrier arrival counter
__device__ unsigned int       g_barsense = 0;                // barrier sense (monotone)

#define F_INF  __int_as_float(0x7F800000)
#define F_NINF __int_as_float((int)0xFF800000)

__device__ __forceinline__ unsigned int packbf(float lo, float hi) {
    return (__float_as_uint(lo) >> 16) | (__float_as_uint(hi) & 0xFFFF0000u);
}

// sense-reversing grid barrier; counter self-resets via atomicInc wrap,
// sense compared by equality -> safe across graph replays.
__device__ __forceinline__ void gbar() {
    __syncthreads();
    if (threadIdx.x == 0) {
        __threadfence();
        unsigned int s = *(volatile unsigned int*)&g_barsense;
        if (atomicInc(&g_barcnt, NBLK - 1) == NBLK - 1) {
            __threadfence();
            *(volatile unsigned int*)&g_barsense = s + 1u;
        } else {
            while (*(volatile unsigned int*)&g_barsense == s) __nanosleep(64);
        }
        __threadfence();
    }
    __syncthreads();
}

// ---------------- role bodies (shared by coop kernel and fallback) ----------
__device__ __forceinline__ void role_mm(const float* __restrict__ X, int c,
                                        int b, int tid, float* smn, float* smx) {
    // init: zero quadrant hists (65536 ints / 512 blocks = 128 each) + scalars
    if (tid < 128) ((int*)&g_qh[c][0][0][0])[b * 128 + tid] = 0;
    if (b == 0 && tid == 0) {
        g_vmin2[c] = 0x7F800000;
        g_vmax2[c] = (int)0xFF800000;
        g_nm[c] = 0u;
    }
    const float4* p = (const float4*)(X + (size_t)c * NPIX);
    int base = b * 8192;
    float vmin = F_INF, vmax = F_NINF;
    #pragma unroll 4
    for (int it = 0; it < 32; ++it) {
        float4 v = p[base + it * 256 + tid];
        if (v.x > 0.f) { vmin = fminf(vmin, v.x); vmax = fmaxf(vmax, v.x); }
        if (v.y > 0.f) { vmin = fminf(vmin, v.y); vmax = fmaxf(vmax, v.y); }
        if (v.z > 0.f) { vmin = fminf(vmin, v.z); vmax = fmaxf(vmax, v.z); }
        if (v.w > 0.f) { vmin = fminf(vmin, v.w); vmax = fmaxf(vmax, v.w); }
    }
    #pragma unroll
    for (int o = 16; o; o >>= 1) {
        vmin = fminf(vmin, __shfl_down_sync(0xffffffffu, vmin, o));
        vmax = fmaxf(vmax, __shfl_down_sync(0xffffffffu, vmax, o));
    }
    if ((tid & 31) == 0) { smn[tid >> 5] = vmin; smx[tid >> 5] = vmax; }
    __syncthreads();
    if (tid == 0) {
        float a = F_INF, bb = F_NINF;
        #pragma unroll
        for (int j = 0; j < 8; j++) { a = fminf(a, smn[j]); bb = fmaxf(bb, smx[j]); }
        g_part[c * MMB + b] = make_float2(a, bb);
    }
    __syncthreads();
}

__device__ __forceinline__ void role_quant(const float* __restrict__ X, int c,
                                           int bx, int tid, int* sh,
                                           float* smn, float* smx, float* sfin) {
    float vmin = F_INF, vmax = F_NINF;
    for (int j = tid; j < MMB; j += 256) {
        float2 pp = g_part[c * MMB + j];
        vmin = fminf(vmin, pp.x); vmax = fmaxf(vmax, pp.y);
    }
    #pragma unroll
    for (int o = 16; o; o >>= 1) {
        vmin = fminf(vmin, __shfl_down_sync(0xffffffffu, vmin, o));
        vmax = fmaxf(vmax, __shfl_down_sync(0xffffffffu, vmax, o));
    }
    if ((tid & 31) == 0) { smn[tid >> 5] = vmin; smx[tid >> 5] = vmax; }
    for (int j = tid; j < QH * BINS; j += 256) sh[j] = 0;
    __syncthreads();
    if (tid == 0) {
        float a = F_INF, b = F_NINF;
        #pragma unroll
        for (int j = 0; j < 8; j++) { a = fminf(a, smn[j]); b = fmaxf(b, smx[j]); }
        sfin[0] = a; sfin[1] = b;
    }
    __syncthreads();
    vmin = sfin[0]; vmax = sfin[1];
    bool  cond = vmax > 0.0f;
    float rng  = fmaxf(vmax - vmin, 1e-12f);
    float a255 = cond ? (255.0f / rng) : 0.0f;
    float b255 = cond ? (-vmin * a255) : 0.0f;

    const float4* p  = (const float4*)(X + (size_t)c * NPIX);
    uchar4*       q8 = (uchar4*)(g_q + (size_t)c * NPIX);
    unsigned char* mp = g_m + (size_t)c * (NPIX / 4);

    int base = bx * 8192;                         // 8 rows of 1024 float4
    unsigned int nm = 0;

    #pragma unroll 4
    for (int it = 0; it < 32; ++it) {
        int i = base + it * 256 + tid;
        float4 v = p[i];
        int tx = (i & 1023) >> 6;                 // 64 float4 per 256-px half
        float xs[4] = {v.x, v.y, v.z, v.w};
        unsigned char r[4]; unsigned int nib = 0;
        #pragma unroll
        for (int k = 0; k < 4; k++) {
            float x = xs[k];
            bool  m = x > 0.0f;
            float t = m ? fmaf(x, a255, b255) : 0.0f;
            float fb = fminf(fmaxf(floorf(t), 0.0f), 255.0f);
            int b = (int)fb;
            atomicAdd(&sh[tx * BINS + b], 1);
            r[k] = (unsigned char)b;
            nib |= (m ? 1u : 0u) << k;
        }
        nm += (unsigned int)__popc(nib);
        uchar4 o; o.x = r[0]; o.y = r[1]; o.z = r[2]; o.w = r[3];
        q8[i] = o;
        mp[i] = (unsigned char)nib;
    }
    __syncthreads();

    int yh = bx >> 5;                             // 32 blocks (8 rows) per 256-row half
    int* gq = &g_qh[c][yh][0][0];
    for (int j = tid; j < QH * BINS; j += 256) {
        int v = sh[j];
        if (v) atomicAdd(&gq[j], v);
    }
    #pragma unroll
    for (int o = 16; o; o >>= 1) nm += __shfl_down_sync(0xffffffffu, nm, o);
    if ((tid & 31) == 0) atomicAdd(&g_nm[c], nm);
    __syncthreads();
}

// ===== cooperative minmax+quant: quant(c) reads X_c from L2 (loaded by mm(c)
// ===== one phase earlier). 4 grid barriers, every block works every phase. ===
__global__ void __launch_bounds__(256, 4) k_coop(const float* __restrict__ X) {
    __shared__ int   sh[QH * BINS];               // 16 KB
    __shared__ float smn[8], smx[8], sfin[2];
    int bid = blockIdx.x, tid = threadIdx.x;

    role_mm(X, 0, bid, tid, smn, smx);
    gbar();
    #pragma unroll 1
    for (int c = 0; c < CC - 1; ++c) {
        role_quant(X, c, bid, tid, sh, smn, smx, sfin);   // X_c from L2
        role_mm(X, c + 1, bid, tid, smn, smx);            // stream X_{c+1}
        gbar();
    }
    role_quant(X, CC - 1, bid, tid, sh, smn, smx, sfin);
}

// ===== fallback: heterogeneous step (proven R10 path) =======================
__global__ void __launch_bounds__(256) k_step(const float* __restrict__ X,
                                              int cq, int cm) {
    __shared__ int   sh[QH * BINS];
    __shared__ float smn[8], smx[8], sfin[2];
    int tid = threadIdx.x;
    if (blockIdx.x >= QBLK) {
        if (cm < 0) return;
        role_mm(X, cm, blockIdx.x - QBLK, tid, smn, smx);
        return;
    }
    if (cq < 0) return;
    role_quant(X, cq, blockIdx.x, tid, sh, smn, smx, sfin);
}

// ------- stats from quadrant hists, clip + redistribute + CDF -> u8 LUT -----
__global__ void k_lut() {
    int c = blockIdx.y, tile = blockIdx.x, t = threadIdx.x;
    __shared__ unsigned int sa[BINS], sb[BINS];
    __shared__ int s[BINS];

    const int* Q = &g_qh[c][0][0][0];
    unsigned int colsum = 0;
    #pragma unroll 8
    for (int k = 0; k < QH * QH; k++) colsum += (unsigned int)Q[k * BINS + t];
    sa[t] = t ? colsum : 0u;                      // nz excludes bin 0
    sb[t] = (unsigned int)t * colsum;             // max 255*16.7M < 2^32
    __syncthreads();
    #pragma unroll
    for (int o = 128; o; o >>= 1) {
        if (t < o) { sa[t] += sa[t + o]; sb[t] += sb[t + o]; }
        __syncthreads();
    }
    unsigned int nz = sa[0], sum = sb[0];

    if (tile == 0 && t == 0) {
        unsigned int unmasked = (unsigned int)NPIX - g_nm[c];
        if (colsum > unmasked) { g_vmin2[c] = 0; g_vmax2[c] = 0; }
    }

    int mean = nz ? (int)(sum / nz) : 0;

    int ty = tile >> 3, tx = tile & 7;
    int q00 = ((2 * ty) * QH + 2 * tx) * BINS;
    int q01 = q00 + BINS;
    int q10 = q00 + QH * BINS;
    int q11 = q10 + BINS;
    int h  = Q[q00 + t] + Q[q01 + t] + Q[q10 + t] + Q[q11 + t];
    if (nz && mean != 0) {                        // hist of `filled`: move bin0 -> mean
        int h0 = Q[q00] + Q[q01] + Q[q10] + Q[q11];
        if (t == mean) h += h0;
        if (t == 0)    h  = 0;
    }

    int exc = max(h - CLV, 0);
    s[t] = exc; __syncthreads();
    #pragma unroll
    for (int o = 128; o; o >>= 1) { if (t < o) s[t] += s[t + o]; __syncthreads(); }
    int excess = s[0];
    __syncthreads();

    h = min(h, CLV);
    int batch = excess >> 8;
    int resid = excess & 255;
    int step  = 256 / max(resid, 1);
    h += batch + (((t % step) == 0 && (t / step) < resid) ? 1 : 0);

    s[t] = h; __syncthreads();
    #pragma unroll
    for (int o = 1; o < 256; o <<= 1) {
        int v = (t >= o) ? s[t - o] : 0;
        __syncthreads();
        s[t] += v;
        __syncthreads();
    }
    float lut = rintf((float)s[t] * (255.0f / (float)AREA));
    lut = fminf(fmaxf(lut, 0.0f), 255.0f);
    g_lut[c][tile][t] = (unsigned char)lut;
}

// ---- analytic pass-2 min/max: eq bilinear per (region, bin), extremes at
// ---- the 4 corner pixels of each 9x9 dual region. Exact. --------------------
__global__ void k_mm2() {
    int c = blockIdx.y, reg = blockIdx.x, t = threadIdx.x;
    int ry = reg / 9, rx = reg % 9;
    int rlo = (ry == 0) ? 0 : 512 * ry - 256;
    int rhi = (ry == 8) ? (HH - 1) : 512 * ry + 255;
    int clo = (rx == 0) ? 0 : 512 * rx - 256;
    int chi = (rx == 8) ? (WW - 1) : 512 * rx + 255;

    bool pres = false;
    if (t > 0) {
        int yh0 = rlo >> 8, yh1 = rhi >> 8;
        int xh0 = clo >> 8, xh1 = chi >> 8;
        for (int yh = yh0; yh <= yh1; ++yh)
            for (int xh = xh0; xh <= xh1; ++xh)
                pres |= (g_qh[c][yh][xh][t] > 0);
    }

    float lmin = F_INF, lmax = F_NINF;
    if (pres) {
        int y0 = max(ry - 1, 0); int y1 = min(y0 + 1, TT - 1);
        int xa = max(rx - 1, 0); int xb = min(xa + 1, TT - 1);
        const unsigned char* L = &g_lut[c][0][0];
        float a0 = (float)L[(y0 * TT + xa) * BINS + t];
        float da = (float)L[(y0 * TT + xb) * BINS + t] - a0;
        float b0 = (float)L[(y1 * TT + xa) * BINS + t];
        float db = (float)L[(y1 * TT + xb) * BINS + t] - b0;

        float fyl = ((float)rlo + 0.5f) * (1.0f / (float)THW) - 0.5f;
        float fyh = ((float)rhi + 0.5f) * (1.0f / (float)THW) - 0.5f;
        float wyv[2] = { fyl - floorf(fyl), fyh - floorf(fyh) };
        float fxl = ((float)clo + 0.5f) * (1.0f / (float)THW) - 0.5f;
        float fxh = ((float)chi + 0.5f) * (1.0f / (float)THW) - 0.5f;
        float wxv[2] = { fxl - floorf(fxl), fxh - floorf(fxh) };

        #pragma unroll
        for (int jy = 0; jy < 2; jy++)
            #pragma unroll
            for (int jx = 0; jx < 2; jx++) {
                float px = fmaf(wxv[jx], da, a0);
                float qx = fmaf(wxv[jx], db, b0);
                float eq = fmaf(wyv[jy], qx - px, px);
                lmin = fminf(lmin, eq);
                lmax = fmaxf(lmax, eq);
            }
    }

    __shared__ float smn[8], smx[8];
    #pragma unroll
    for (int o = 16; o; o >>= 1) {
        lmin = fminf(lmin, __shfl_down_sync(0xffffffffu, lmin, o));
        lmax = fmaxf(lmax, __shfl_down_sync(0xffffffffu, lmax, o));
    }
    if ((t & 31) == 0) { smn[t >> 5] = lmin; smx[t >> 5] = lmax; }
    __syncthreads();
    if (t == 0) {
        float a = F_INF, b = F_NINF;
        #pragma unroll
        for (int j = 0; j < 8; j++) { a = fminf(a, smn[j]); b = fmaxf(b, smx[j]); }
        if (b != F_NINF) {
            a = a * (1.0f / 255.0f);              // y = eq/255 (monotone)
            b = b * (1.0f / 255.0f);
            atomicMin(&g_vmin2[c], __float_as_int(a));
            atomicMax(&g_vmax2[c], __float_as_int(b));
        }
    }
}

// -------- apply: 8-row strips, bf16-packed strip LUT, streaming stores -------
__global__ void __launch_bounds__(256) k_apply(float* __restrict__ out) {
    int c = blockIdx.y, s = blockIdx.x, tid = threadIdx.x;
    int r0 = s * SROWS;
    __shared__ uint2 lutP[9 * BINS];              // 18 KB

    float fy0 = ((float)r0 + 0.5f) * (1.0f / (float)THW) - 0.5f;
    int y0 = min(max((int)floorf(fy0), 0), TT - 1);
    int y1 = min(y0 + 1, TT - 1);

    const unsigned char* L = &g_lut[c][0][0];
    #pragma unroll
    for (int e0 = 0; e0 < 9 * BINS; e0 += 256) {
        int e = e0 + tid;
        int ix = e >> 8, f = e & 255;
        int xa = max(ix - 1, 0);
        int xb = min(xa + 1, TT - 1);
        if (f == 0) {
            lutP[e] = make_uint2(0u, 0u);         // eq exactly 0 for bin 0
        } else {
            float a0 = (float)L[(y0 * TT + xa) * BINS + f];
            float a1 = (float)L[(y0 * TT + xb) * BINS + f];
            float b0 = (float)L[(y1 * TT + xa) * BINS + f];
            float b1 = (float)L[(y1 * TT + xb) * BINS + f];
            lutP[e] = make_uint2(packbf(a0, a1 - a0), packbf(b0, b1 - b0));
        }
    }
    __syncthreads();

    float K1 = 0.0f, K2 = 0.0039215686f;
    {
        float vmax2 = __int_as_float(g_vmax2[c]);
        float vmin2 = __int_as_float(g_vmin2[c]);
        if (vmax2 > 0.0f) {
            float rng2 = fmaxf(vmax2 - vmin2, 1e-12f);
            float k1 = 0.99607843137f / rng2;
            K1 = k1 * (1.0f / 255.0f);
            K2 = 0.0039215686f - vmin2 * k1;
        }
    }

    float fx0 = ((float)(tid * 16) + 0.5f) * (1.0f / (float)THW) - 0.5f;
    float ffx = floorf(fx0);
    float wx0 = fx0 - ffx;
    const uint2* rowL = lutP + ((int)ffx + 1) * BINS;
    float wxv[16];
    #pragma unroll
    for (int j = 0; j < 16; j++) wxv[j] = fmaf((float)j, 1.0f / (float)THW, wx0);

    int rowstride = WW / 16;
    size_t base16 = ((size_t)c * NPIX + (size_t)r0 * WW) >> 4;
    const uint4* qp = ((const uint4*)g_q) + base16 + tid;
    const unsigned int* mp = ((const unsigned int*)g_m) + base16 + tid;
    float4* op = ((float4*)out) + (((size_t)c * NPIX + (size_t)r0 * WW) >> 2) + tid * 4;

    for (int rr = 0; rr < SROWS; ++rr) {
        float fyr = ((float)(r0 + rr) + 0.5f) * (1.0f / (float)THW) - 0.5f;
        float wy = fyr - floorf(fyr);
        uint4 qw = qp[rr * rowstride];
        unsigned int mw = mp[rr * rowstride];
        unsigned int wv[4] = {qw.x, qw.y, qw.z, qw.w};
        #pragma unroll
        for (int w = 0; w < 4; w++) {
            float res[4];
            #pragma unroll
            for (int k = 0; k < 4; k++) {
                unsigned int v = (wv[w] >> (8 * k)) & 255u;
                uint2 e = rowL[v];
                float a0 = __int_as_float(e.x << 16);
                float da = __int_as_float(e.x & 0xFFFF0000u);
                float b0 = __int_as_float(e.y << 16);
                float db = __int_as_float(e.y & 0xFFFF0000u);
                float wx = wxv[w * 4 + k];
                float px = fmaf(wx, da, a0);
                float qx = fmaf(wx, db, b0);
                float eq = fmaf(wy, qx - px, px);
                float sc = fmaf(eq, K1, K2);
                res[k] = ((mw >> (8 * w + k)) & 1u) ? sc : 0.0f;
            }
            float4 o4; o4.x = res[0]; o4.y = res[1]; o4.z = res[2]; o4.w = res[3];
            __stcs(&op[(size_t)rr * (WW / 4) + w], o4);   // never re-read: stream
        }
    }
}

// ---------------------------------------------------------------------------
extern "C" void kernel_launch(void* const* d_in, const int* in_sizes, int n_in,
                              void* d_out, int out_size) {
    const float* X = (const float*)d_in[0];
    float* out = (float*)d_out;

    // coop kernel needs all NBLK blocks co-resident (grid barriers)
    static int can_coop = -1;
    if (can_coop < 0) {
        int nb = 0;
        cudaOccupancyMaxActiveBlocksPerMultiprocessor(&nb, k_coop, 256, 0);
        int dev = 0, sms = 0;
        cudaGetDevice(&dev);
        cudaDeviceGetAttribute(&sms, cudaDevAttrMultiProcessorCount, dev);
        can_coop = ((long long)nb * sms >= NBLK) ? 1 : 0;
    }

    if (can_coop) {
        k_coop<<<NBLK, 256>>>(X);
    } else {
        k_step<<<QBLK + MMB, 256>>>(X, -1, 0);
        k_step<<<QBLK + MMB, 256>>>(X,  0, 1);
        k_step<<<QBLK + MMB, 256>>>(X,  1, 2);
        k_step<<<QBLK + MMB, 256>>>(X,  2, 3);
        k_step<<<QBLK + MMB, 256>>>(X,  3, -1);
    }

    dim3 g3(TT*TT, CC);      k_lut  <<<g3, 256>>>();
    dim3 g5(81, CC);         k_mm2  <<<g5, 256>>>();
    dim3 g4(HH/SROWS, CC);   k_apply<<<g4, 256>>>(out);
}